// round 17
// baseline (speedup 1.0000x reference)
#include <cuda_runtime.h>
#include <cuda_fp16.h>
#include <mma.h>
#include <cstdint>

using namespace nvcuda;

#define N_NODES 131072
#define P_NODES 4096
#define B_GR    32
#define E_EDGES 2097152
#define IN_DIM  64
#define HID     128
#define OUT_DIM 16
#define CAP     64
#define EPSV    1e-5f
#define SLOPE   0.01f

// ---------------- scratch (device globals; no allocations allowed) ----------
__device__ int    g_deg_src[N_NODES];
__device__ int    g_cursor[N_NODES];                 // dst degree after build
__device__ int2   g_csre[(size_t)N_NODES * CAP];     // packed {src, half2(ew,ew)}
__device__ __half g_x16[(size_t)N_NODES * IN_DIM];   // fp16 features * rs_src
__device__ __half g_agg1[(size_t)N_NODES * IN_DIM];
__device__ __half g_agg2[(size_t)N_NODES * HID];
__device__ __half g_w1t[HID * IN_DIM];               // W1^T  [n][k] fp16
__device__ __half g_w2t[HID * HID];                  // W2^T  [n][k] fp16
__device__ __half g_h1pre[(size_t)N_NODES * HID];    // pre-norm h1 (fp16)
__device__ __half g_h1h[(size_t)N_NODES * HID];      // normalized h1 * rs_src (fp16)
__device__ __half g_h2pre[(size_t)N_NODES * HID];    // pre-norm h2 (fp16)
__device__ float  g_stats1[2 * HID];
__device__ float  g_stats2[2 * HID];
__device__ float  g_r[B_GR * 2 * HID];

__device__ __forceinline__ __half2 h2red(__half2 a, int m) {
    uint32_t u = *(uint32_t*)&a;
    uint32_t o = __shfl_xor_sync(0xffffffffu, u, m);
    return __hadd2(a, *(__half2*)&o);
}
__device__ __forceinline__ __half2 u2h(uint32_t u) { return *(__half2*)&u; }

// ---------------- setup -----------------------------------------------------

__global__ void k_zero() {
    int i = blockIdx.x * blockDim.x + threadIdx.x;
    if (i < N_NODES) { g_deg_src[i] = 0; g_cursor[i] = 0; }
    if (i < 2 * HID) { g_stats1[i] = 0.f; g_stats2[i] = 0.f; }
    if (i < B_GR * 2 * HID) { g_r[i] = 0.f; }
}

// 8 edges/thread; weight pre-converted to duplicated half2.
__global__ __launch_bounds__(256) void k_build(const int* __restrict__ src,
                                               const int* __restrict__ dst,
                                               const float* __restrict__ ew) {
    int e8 = (blockIdx.x * 256 + threadIdx.x) * 8;
    int4   sa = *(const int4*)&src[e8],   sb = *(const int4*)&src[e8 + 4];
    int4   da = *(const int4*)&dst[e8],   db = *(const int4*)&dst[e8 + 4];
    float4 wa = *(const float4*)&ew[e8],  wb = *(const float4*)&ew[e8 + 4];

    int s[8] = {sa.x, sa.y, sa.z, sa.w, sb.x, sb.y, sb.z, sb.w};
    int d[8] = {da.x, da.y, da.z, da.w, db.x, db.y, db.z, db.w};
    float wv[8] = {wa.x, wa.y, wa.z, wa.w, wb.x, wb.y, wb.z, wb.w};

    int p[8];
    #pragma unroll
    for (int u = 0; u < 8; u++) p[u] = atomicAdd(&g_cursor[d[u]], 1);
    #pragma unroll
    for (int u = 0; u < 8; u++) atomicAdd(&g_deg_src[s[u]], 1);
    #pragma unroll
    for (int u = 0; u < 8; u++) {
        uint32_t h = (uint32_t)__half_as_ushort(__float2half(wv[u])) * 0x00010001u;
        if (p[u] < CAP) g_csre[(size_t)d[u] * CAP + p[u]] = make_int2(s[u], (int)h);
    }
}

// pad CSR rows to multiple of 32 with {src=0, w=0} sentinels. lane = node.
__global__ __launch_bounds__(256) void k_pad() {
    int v = blockIdx.x * 256 + threadIdx.x;
    int deg = min(g_cursor[v], CAP);
    int deg32 = (deg + 31) & ~31;
    int2* ce = &g_csre[(size_t)v * CAP];
    for (int i = deg; i < deg32; i++) ce[i] = make_int2(0, 0);
}

// blocks [0,4096): features -> fp16 * rsqrt(deg_src); 8 floats/thread.
// block 4096: transpose W1,W2 to fp16 K-major.
__global__ __launch_bounds__(256) void k_prep(const float* __restrict__ x,
                                              const float* __restrict__ W1,
                                              const float* __restrict__ W2) {
    int b = blockIdx.x, t = threadIdx.x;
    if (b < 4096) {
        int i0 = b * 2048 + t * 8;
        int row = i0 >> 6;
        float rs = rsqrtf((float)max(g_deg_src[row], 1));
        float4 a = *(const float4*)&x[i0];
        float4 c = *(const float4*)&x[i0 + 4];
        uint4 o;
        __half2 b0 = __floats2half2_rn(a.x * rs, a.y * rs);
        __half2 b1 = __floats2half2_rn(a.z * rs, a.w * rs);
        __half2 b2 = __floats2half2_rn(c.x * rs, c.y * rs);
        __half2 b3 = __floats2half2_rn(c.z * rs, c.w * rs);
        o.x = *(uint32_t*)&b0; o.y = *(uint32_t*)&b1;
        o.z = *(uint32_t*)&b2; o.w = *(uint32_t*)&b3;
        *(uint4*)&g_x16[i0] = o;
    } else {
        for (int i = t; i < HID * IN_DIM; i += 256) {
            int n = i / IN_DIM, k = i % IN_DIM;
            g_w1t[i] = __float2half(W1[k * HID + n]);
        }
        for (int i = t; i < HID * HID; i += 256) {
            int n = i / HID, k = i % HID;
            g_w2t[i] = __float2half(W2[k * HID + n]);
        }
    }
}

// ---------------- aggregation: padded CSR, paired meta, HFMA2 ----------------
// agg1: row = 128B = 8 lanes x uint4. Quarter-warp qw owns edge pairs
// {8u+2qw, 8u+2qw+1}; 4 uint4 meta loads + 8 feature loads per 32-edge batch.
__global__ __launch_bounds__(256) void k_agg1() {
    int tid = threadIdx.x, w = tid >> 5, lane = tid & 31;
    int qw = lane >> 3, fl = lane & 7;
    int vb = blockIdx.x * 32 + w * 4;
    #pragma unroll
    for (int nn = 0; nn < 4; nn++) {
        int v = vb + nn;
        int degf = g_cursor[v];
        int deg32 = (min(degf, CAP) + 31) & ~31;
        const int2* ce = &g_csre[(size_t)v * CAP];
        __half2 ac0 = __float2half2_rn(0.f), ac1 = ac0, ac2 = ac0, ac3 = ac0;
        for (int i = 0; i < deg32; i += 32) {
            uint4 mm[4];
            #pragma unroll
            for (int u = 0; u < 4; u++)
                mm[u] = *(const uint4*)&ce[i + 8 * u + 2 * qw];
            uint4 fa[4], fb[4];
            #pragma unroll
            for (int u = 0; u < 4; u++) {
                fa[u] = *(const uint4*)(g_x16 + (size_t)(int)mm[u].x * IN_DIM + fl * 8);
                fb[u] = *(const uint4*)(g_x16 + (size_t)(int)mm[u].z * IN_DIM + fl * 8);
            }
            #pragma unroll
            for (int u = 0; u < 4; u++) {
                __half2 wa = u2h(mm[u].y), wb = u2h(mm[u].w);
                ac0 = __hfma2(wa, u2h(fa[u].x), ac0);
                ac1 = __hfma2(wa, u2h(fa[u].y), ac1);
                ac2 = __hfma2(wa, u2h(fa[u].z), ac2);
                ac3 = __hfma2(wa, u2h(fa[u].w), ac3);
                ac0 = __hfma2(wb, u2h(fb[u].x), ac0);
                ac1 = __hfma2(wb, u2h(fb[u].y), ac1);
                ac2 = __hfma2(wb, u2h(fb[u].z), ac2);
                ac3 = __hfma2(wb, u2h(fb[u].w), ac3);
            }
        }
        ac0 = h2red(h2red(ac0, 8), 16);
        ac1 = h2red(h2red(ac1, 8), 16);
        ac2 = h2red(h2red(ac2, 8), 16);
        ac3 = h2red(h2red(ac3, 8), 16);
        if (qw == 0) {
            __half2 rdh = __float2half2_rn(rsqrtf((float)max(degf, 1)));
            ac0 = __hmul2(ac0, rdh);
            ac1 = __hmul2(ac1, rdh);
            ac2 = __hmul2(ac2, rdh);
            ac3 = __hmul2(ac3, rdh);
            uint4 o;
            o.x = *(uint32_t*)&ac0; o.y = *(uint32_t*)&ac1;
            o.z = *(uint32_t*)&ac2; o.w = *(uint32_t*)&ac3;
            *(uint4*)&g_agg1[(size_t)v * IN_DIM + fl * 8] = o;
        }
    }
}

// agg2: row = 256B = 16 lanes x uint4. Half-warp hw owns edge pairs
// {4u+2hw, 4u+2hw+1}; 4 uint4 meta + 8 feature loads per 16-edge batch.
__global__ __launch_bounds__(256) void k_agg2() {
    int tid = threadIdx.x, w = tid >> 5, lane = tid & 31;
    int hw = lane >> 4, fl = lane & 15;
    int vb = blockIdx.x * 32 + w * 4;
    #pragma unroll
    for (int nn = 0; nn < 4; nn++) {
        int v = vb + nn;
        int degf = g_cursor[v];
        int deg16 = (min(degf, CAP) + 15) & ~15;
        const int2* ce = &g_csre[(size_t)v * CAP];
        __half2 ac0 = __float2half2_rn(0.f), ac1 = ac0, ac2 = ac0, ac3 = ac0;
        for (int i = 0; i < deg16; i += 16) {
            uint4 mm[4];
            #pragma unroll
            for (int u = 0; u < 4; u++)
                mm[u] = *(const uint4*)&ce[i + 4 * u + 2 * hw];
            uint4 fa[4], fb[4];
            #pragma unroll
            for (int u = 0; u < 4; u++) {
                fa[u] = *(const uint4*)(g_h1h + (size_t)(int)mm[u].x * HID + fl * 8);
                fb[u] = *(const uint4*)(g_h1h + (size_t)(int)mm[u].z * HID + fl * 8);
            }
            #pragma unroll
            for (int u = 0; u < 4; u++) {
                __half2 wa = u2h(mm[u].y), wb = u2h(mm[u].w);
                ac0 = __hfma2(wa, u2h(fa[u].x), ac0);
                ac1 = __hfma2(wa, u2h(fa[u].y), ac1);
                ac2 = __hfma2(wa, u2h(fa[u].z), ac2);
                ac3 = __hfma2(wa, u2h(fa[u].w), ac3);
                ac0 = __hfma2(wb, u2h(fb[u].x), ac0);
                ac1 = __hfma2(wb, u2h(fb[u].y), ac1);
                ac2 = __hfma2(wb, u2h(fb[u].z), ac2);
                ac3 = __hfma2(wb, u2h(fb[u].w), ac3);
            }
        }
        ac0 = h2red(ac0, 16);
        ac1 = h2red(ac1, 16);
        ac2 = h2red(ac2, 16);
        ac3 = h2red(ac3, 16);
        if (hw == 0) {
            __half2 rdh = __float2half2_rn(rsqrtf((float)max(degf, 1)));
            ac0 = __hmul2(ac0, rdh);
            ac1 = __hmul2(ac1, rdh);
            ac2 = __hmul2(ac2, rdh);
            ac3 = __hmul2(ac3, rdh);
            uint4 o;
            o.x = *(uint32_t*)&ac0; o.y = *(uint32_t*)&ac1;
            o.z = *(uint32_t*)&ac2; o.w = *(uint32_t*)&ac3;
            *(uint4*)&g_agg2[(size_t)v * HID + fl * 8] = o;
        }
    }
}

// ---------------- WMMA (fp16) GEMM + fused GraphNorm stats -------------------
__global__ __launch_bounds__(256) void k_gemm(int layer) {
    extern __shared__ __half smb[];
    const int K   = (layer == 1) ? IN_DIM : HID;
    const int pitch = K + 8;
    __half* sA = smb;                              // [128][pitch]
    __half* sB = smb + 128 * pitch;                // [128][pitch]
    const __half* Ag = (layer == 1) ? g_agg1 : g_agg2;
    const __half* Bg = (layer == 1) ? g_w1t  : g_w2t;
    int tid = threadIdx.x;
    size_t m0 = (size_t)blockIdx.x * 128;

    int vecs = K / 8;                              // uint4 = 8 fp16
    for (int i = tid; i < 128 * vecs; i += 256) {
        int r = i / vecs, c = i % vecs;
        *(uint4*)&sA[r * pitch + c * 8] = *(const uint4*)&Ag[(m0 + r) * K + c * 8];
        *(uint4*)&sB[r * pitch + c * 8] = *(const uint4*)&Bg[(size_t)r * K + c * 8];
    }
    __syncthreads();

    int w = tid >> 5;
    wmma::fragment<wmma::accumulator, 16, 16, 16, float> acc[8];
    #pragma unroll
    for (int n = 0; n < 8; n++) wmma::fill_fragment(acc[n], 0.f);

    for (int k = 0; k < K; k += 16) {
        wmma::fragment<wmma::matrix_a, 16, 16, 16, __half, wmma::row_major> fa;
        wmma::load_matrix_sync(fa, &sA[(w * 16) * pitch + k], pitch);
        #pragma unroll
        for (int n = 0; n < 8; n++) {
            wmma::fragment<wmma::matrix_b, 16, 16, 16, __half, wmma::col_major> fb;
            wmma::load_matrix_sync(fb, &sB[(n * 16) * pitch + k], pitch);
            wmma::mma_sync(acc[n], fa, fb, acc[n]);
        }
    }

    // ---- epilogue: stage to smem, fused stats, fp16 store ----
    __syncthreads();
    float* Hs = (float*)smb;                       // [128][128] = 64 KB
    #pragma unroll
    for (int n = 0; n < 8; n++)
        wmma::store_matrix_sync(&Hs[(w * 16) * HID + n * 16], acc[n], HID,
                                wmma::mem_row_major);
    __syncthreads();

    __half* H  = (layer == 1) ? g_h1pre : g_h2pre;
    float*  st = (layer == 1) ? g_stats1 : g_stats2;

    int col = tid & 127, half = tid >> 7;
    float s = 0.f, ss = 0.f;
    #pragma unroll 8
    for (int r = 0; r < 64; r++) {
        float vv = Hs[(half * 64 + r) * HID + col];
        s += vv;
        ss += vv * vv;
    }
    atomicAdd(&st[col], s);
    atomicAdd(&st[HID + col], ss);

    for (int i = tid; i < 128 * 32; i += 256) {
        int r = i >> 5, c = i & 31;
        float4 f = ((const float4*)&Hs[r * HID])[c];
        __half2 h0 = __floats2half2_rn(f.x, f.y);
        __half2 h1 = __floats2half2_rn(f.z, f.w);
        uint2 o;
        o.x = *(uint32_t*)&h0;
        o.y = *(uint32_t*)&h1;
        ((uint2*)&H[(m0 + r) * HID])[c] = o;
    }
}

// ---------------- norm / readout ---------------------------------------------
__global__ void k_norm(int layer,
                       const float* __restrict__ gamma, const float* __restrict__ beta,
                       const float* __restrict__ alpha) {
    __shared__ float sRs[64];
    int j = threadIdx.x;
    int b = blockIdx.x;
    const float* stats = (layer == 1) ? g_stats1 : g_stats2;
    const __half* hpre = (layer == 1) ? g_h1pre : g_h2pre;
    int rcol   = (layer == 1) ? 0 : HID;
    int writeH = (layer == 1) ? 1 : 0;

    if (writeH && j < 64) sRs[j] = rsqrtf((float)max(g_deg_src[b * 64 + j], 1));
    __syncthreads();

    const float invN = 1.0f / (float)N_NODES;
    float mu  = stats[j] * invN;
    float ex2 = stats[HID + j] * invN;
    float al  = alpha[j];
    float var = ex2 + mu * mu * (al * al - 2.f * al);
    float istd = rsqrtf(var + EPSV);
    float ga = gamma[j] * istd;
    float be = beta[j];
    float amu = al * mu;

    int g = (b * 64) / P_NODES;
    const __half* in = &hpre[(size_t)b * 64 * HID];
    __half* out = &g_h1h[(size_t)b * 64 * HID];
    float rsum = 0.f;
    #pragma unroll 4
    for (int r = 0; r < 64; r++) {
        float v = __half2float(in[r * HID + j]);
        float c = (v - amu) * ga + be;
        float y = c > 0.f ? c : SLOPE * c;
        if (writeH) out[r * HID + j] = __float2half(y * sRs[r]);
        rsum += y;
    }
    atomicAdd(&g_r[g * (2 * HID) + rcol + j], rsum);
}

__global__ void k_final(const float* __restrict__ Wc, float* __restrict__ out) {
    int t = threadIdx.x;
    int b = t >> 4, o = t & 15;
    const float* rb = &g_r[b * 2 * HID];
    const float* wr = &Wc[o * 2 * HID];
    float s = 0.f;
    #pragma unroll 8
    for (int k = 0; k < 2 * HID; k++) s += rb[k] * wr[k];
    out[b * OUT_DIM + o] = s * (1.0f / (float)P_NODES);
}

// ---------------- launch -----------------------------------------------------

extern "C" void kernel_launch(void* const* d_in, const int* in_sizes, int n_in,
                              void* d_out, int out_size) {
    const float* features = (const float*)d_in[0];
    const float* ew       = (const float*)d_in[1];
    const int*   src      = (const int*)d_in[2];
    const int*   dst      = (const int*)d_in[3];
    const float* W1       = (const float*)d_in[4];
    const float* W2       = (const float*)d_in[5];
    const float* Wc       = (const float*)d_in[6];
    const float* gamma1   = (const float*)d_in[7];
    const float* beta1    = (const float*)d_in[8];
    const float* alpha1   = (const float*)d_in[9];
    const float* gamma2   = (const float*)d_in[10];
    const float* beta2    = (const float*)d_in[11];
    const float* alpha2   = (const float*)d_in[12];
    float* out = (float*)d_out;

    const int smem1 = 128 * 128 * 4;               // 65536
    const int smem2 = 2 * 128 * (HID + 8) * 2;     // 69632
    cudaFuncSetAttribute(k_gemm, cudaFuncAttributeMaxDynamicSharedMemorySize, smem2);

    k_zero<<<N_NODES / 256, 256>>>();
    k_build<<<E_EDGES / 2048, 256>>>(src, dst, ew);
    k_pad<<<N_NODES / 256, 256>>>();
    k_prep<<<4097, 256>>>(features, W1, W2);

    k_agg1<<<N_NODES / 32, 256>>>();
    k_gemm<<<N_NODES / 128, 256, smem1>>>(1);
    k_norm<<<2048, 128>>>(1, gamma1, beta1, alpha1);

    k_agg2<<<N_NODES / 32, 256>>>();
    k_gemm<<<N_NODES / 128, 256, smem2>>>(2);
    k_norm<<<2048, 128>>>(2, gamma2, beta2, alpha2);

    k_final<<<1, 512>>>(Wc, out);
}